// round 16
// baseline (speedup 1.0000x reference)
#include <cuda_runtime.h>
#include <math.h>

#define NBLOCKS 128
#define NTHREADS 512
#define SAMP 8
#define CC 64
#define HH 128
#define MAX_IT 500
#define TOLV 1e-3f
#define WZ1_S 132   // row stride (floats): mult of 4, ≡4 mod 32 -> LDS.128 conflict-free
#define WY_S  68

typedef unsigned long long u64t;

struct __align__(16) Smem {
    float wz1[HH * WZ1_S];     // clipped Wz1 [j][k]
    float wy0[HH * WY_S];      // [j][c]
    float wy1[HH * WY_S];      // [j][c]
    float wz2[HH];             // clipped
    float wy2[CC];
    float by0[HH];
    float by1[HH];
    float z  [SAMP][CC];
    float x1 [SAMP][CC];
    float x1p[SAMP][CC];       // x1 BEFORE this iteration's update (stop rollback)
    float h0v[SAMP][HH];       // h0 fwd, v~ bwd
    float s0 [SAMP][HH];       // sigmoid(a0)
    float s1u[SAMP][HH];       // u~ = wz2 * sigmoid(a1)
    float scratch[4096];       // stage partials
    float stepv[MAX_IT];       // 2/(i+1) table
    float a2  [SAMP];
    float s2  [SAMP];
    float nrm2[SAMP];
    float by2;
    int   flag;
};

__device__ unsigned int g_bar_count = 0;
__device__ unsigned int g_bar_gen   = 0;
__device__ float        g_err[MAX_IT];
__device__ unsigned int g_cnt[MAX_IT];

__device__ __forceinline__ u64t pk2(float lo, float hi) {
    u64t r; asm("mov.b64 %0, {%1,%2};" : "=l"(r) : "f"(lo), "f"(hi)); return r;
}
__device__ __forceinline__ void fma2(u64t& d, u64t a, u64t b) {
    asm("fma.rn.f32x2 %0, %1, %2, %0;" : "+l"(d) : "l"(a), "l"(b));
}
__device__ __forceinline__ float rsum2(u64t a) {
    float lo, hi; asm("mov.b64 {%0,%1}, %2;" : "=f"(lo), "=f"(hi) : "l"(a));
    return lo + hi;
}

// EXACT activations (R13 proved approximations delay convergence)
__device__ __forceinline__ void act2(float a, float& sp, float& sg) {
    float e   = __expf(-fabsf(a));
    float inv = __fdividef(1.0f, 1.0f + e);
    sg = (a >= 0.0f) ? inv : e * inv;
    sp = fmaxf(a, 0.0f) + __logf(1.0f + e);
}
__device__ __forceinline__ float sig_f(float a) {
    float e   = __expf(-fabsf(a));
    float inv = __fdividef(1.0f, 1.0f + e);
    return (a >= 0.0f) ? inv : e * inv;
}

// startup-only sense-reversal barrier (device globals persist across graph replays)
__device__ __forceinline__ void grid_barrier() {
    __syncthreads();
    if (threadIdx.x == 0) {
        __threadfence();
        unsigned int gen = *((volatile unsigned int*)&g_bar_gen);
        if (atomicAdd(&g_bar_count, 1u) == (unsigned)(NBLOCKS - 1)) {
            atomicExch(&g_bar_count, 0u);
            __threadfence();
            atomicAdd(&g_bar_gen, 1u);
        } else {
            while (*((volatile unsigned int*)&g_bar_gen) == gen) __nanosleep(32);
        }
    }
    __syncthreads();
}

extern "C" __global__ void __launch_bounds__(NTHREADS, 1)
blnn_kernel(const float* __restrict__ x,   const float* __restrict__ Wy0,
            const float* __restrict__ by0, const float* __restrict__ Wy1,
            const float* __restrict__ by1, const float* __restrict__ Wz1,
            const float* __restrict__ Wy2, const float* __restrict__ by2,
            const float* __restrict__ Wz2, float* __restrict__ out)
{
    extern __shared__ __align__(16) float smem_raw[];
    Smem* sm = (Smem*)smem_raw;
    const int tid  = threadIdx.x;
    const int bx   = blockIdx.x;
    const int lane = tid & 31;
    const int warp = tid >> 5;

    // ---- weights -> SMEM (padded strides, clip Wz* at 0) ----
    for (int idx = tid; idx < HH * HH; idx += NTHREADS) {
        int jj = idx >> 7, kk = idx & (HH - 1);
        sm->wz1[jj * WZ1_S + kk] = fmaxf(Wz1[idx], 0.0f);
    }
    for (int idx = tid; idx < HH * CC; idx += NTHREADS) {
        int jj = idx >> 6, c2 = idx & (CC - 1);
        sm->wy0[jj * WY_S + c2] = Wy0[idx];
        sm->wy1[jj * WY_S + c2] = Wy1[idx];
    }
    if (tid < HH) {
        sm->wz2[tid] = fmaxf(Wz2[tid], 0.0f);
        sm->by0[tid] = by0[tid];
        sm->by1[tid] = by1[tid];
    }
    if (tid < CC) sm->wy2[tid] = Wy2[tid];
    if (tid == 0) sm->by2 = by2[0];
    for (int idx = tid; idx < MAX_IT; idx += NTHREADS)
        sm->stepv[idx] = __fdividef(2.0f, (float)(idx + 1));

    const int sbase = bx * SAMP;
    for (int idx = tid; idx < SAMP * CC; idx += NTHREADS) {
        sm->z [idx >> 6][idx & 63] = x[sbase * CC + idx];
        sm->x1[idx >> 6][idx & 63] = 1.0f;
    }
    // re-zero our stripe of the per-iteration accumulators (graph replays!)
    if (tid == 0) {
        for (int idx = bx; idx < MAX_IT; idx += NBLOCKS) {
            *((volatile float*)&g_err[idx]) = 0.0f;
            *((volatile unsigned int*)&g_cnt[idx]) = 0u;
        }
    }
    grid_barrier();   // slots zeroed everywhere before any block posts

    const int j  = tid & (HH - 1);   // stages 1/2/5: output feature index
    const int q  = tid >> 7;         // 0..3: reduction quarter
    const int c6 = tid & (CC - 1);   // stage 6: output c
    const int o6 = tid >> 6;         // 0..7: stage 6 reduction eighth / sample

    // ---- register-resident weights for stages 5 & 6 (thread-invariant) ----
    u64t w5[16];
    {
        const int jb = 32 * q;
        #pragma unroll
        for (int jq = 0; jq < 32; jq += 4) {
            const float* col = &sm->wz1[(jb + jq) * WZ1_S + j];
            w5[(jq >> 2) * 2]     = pk2(col[0],         col[WZ1_S]);
            w5[(jq >> 2) * 2 + 1] = pk2(col[2 * WZ1_S], col[3 * WZ1_S]);
        }
    }
    u64t w6[16];
    {
        const int kb = 16 * o6;
        #pragma unroll
        for (int kq = 0; kq < 16; kq += 4) {
            int k = kb + kq;
            const float* p0 = &sm->wy0[k * WY_S + c6];
            const float* p1 = &sm->wy1[k * WY_S + c6];
            w6[kq]     = pk2(p0[0],        p0[WY_S]);
            w6[kq + 1] = pk2(p0[2 * WY_S], p0[3 * WY_S]);
            w6[kq + 2] = pk2(p1[0],        p1[WY_S]);
            w6[kq + 3] = pk2(p1[2 * WY_S], p1[3 * WY_S]);
        }
    }

    bool usePrev = false;
    int it = 0;
    for (; it < MAX_IT; ++it) {
        if (tid < SAMP) { sm->a2[tid] = 0.0f; sm->nrm2[tid] = 0.0f; }

        // ================= stage 1: a0 = Wy0 x1 + by0 =================
        {
            u64t acc[SAMP];
            #pragma unroll
            for (int s = 0; s < SAMP; s++) acc[s] = 0ull;
            const float* wrow = &sm->wy0[j * WY_S + 16 * q];
            const int cb = 16 * q;
            #pragma unroll
            for (int cq = 0; cq < 16; cq += 4) {
                ulonglong2 w = *(const ulonglong2*)(wrow + cq);
                #pragma unroll
                for (int s = 0; s < SAMP; s++) {
                    ulonglong2 xv = *(const ulonglong2*)&sm->x1[s][cb + cq];
                    fma2(acc[s], w.x, xv.x);
                    fma2(acc[s], w.y, xv.y);
                }
            }
            #pragma unroll
            for (int s = 0; s < SAMP; s++)
                sm->scratch[q * 1024 + s * HH + j] = rsum2(acc[s]);
            __syncthreads();
            #pragma unroll
            for (int t = 0; t < 2; t++) {
                int s = 2 * q + t;
                float a = sm->scratch[0 * 1024 + s * HH + j]
                        + sm->scratch[1 * 1024 + s * HH + j]
                        + sm->scratch[2 * 1024 + s * HH + j]
                        + sm->scratch[3 * 1024 + s * HH + j] + sm->by0[j];
                float sp, sg;
                act2(a, sp, sg);
                sm->h0v[s][j] = sp;
                sm->s0 [s][j] = sg;
            }
        }
        __syncthreads();

        // ====== stage 2: a1 = Wz1p h0 + Wy1 x1 + by1 ; u~ ; a2 partial ======
        {
            u64t acc[SAMP];
            #pragma unroll
            for (int s = 0; s < SAMP; s++) acc[s] = 0ull;
            const float* wzrow = &sm->wz1[j * WZ1_S + 32 * q];
            const int kb = 32 * q;
            #pragma unroll
            for (int kq = 0; kq < 32; kq += 4) {
                ulonglong2 w = *(const ulonglong2*)(wzrow + kq);
                #pragma unroll
                for (int s = 0; s < SAMP; s++) {
                    ulonglong2 hv = *(const ulonglong2*)&sm->h0v[s][kb + kq];
                    fma2(acc[s], w.x, hv.x);
                    fma2(acc[s], w.y, hv.y);
                }
            }
            const float* wyrow = &sm->wy1[j * WY_S + 16 * q];
            const int cb = 16 * q;
            #pragma unroll
            for (int cq = 0; cq < 16; cq += 4) {
                ulonglong2 w = *(const ulonglong2*)(wyrow + cq);
                #pragma unroll
                for (int s = 0; s < SAMP; s++) {
                    ulonglong2 xv = *(const ulonglong2*)&sm->x1[s][cb + cq];
                    fma2(acc[s], w.x, xv.x);
                    fma2(acc[s], w.y, xv.y);
                }
            }
            #pragma unroll
            for (int s = 0; s < SAMP; s++)
                sm->scratch[q * 1024 + s * HH + j] = rsum2(acc[s]);
            __syncthreads();
            const float wz2j = sm->wz2[j];
            float pv[2];
            #pragma unroll
            for (int t = 0; t < 2; t++) {
                int s = 2 * q + t;
                float a = sm->scratch[0 * 1024 + s * HH + j]
                        + sm->scratch[1 * 1024 + s * HH + j]
                        + sm->scratch[2 * 1024 + s * HH + j]
                        + sm->scratch[3 * 1024 + s * HH + j] + sm->by1[j];
                float sp, sg;
                act2(a, sp, sg);
                sm->s1u[s][j] = wz2j * sg;     // u~
                pv[t] = wz2j * sp;             // wz2 * h1
            }
            #pragma unroll
            for (int off = 16; off; off >>= 1) {
                pv[0] += __shfl_down_sync(0xffffffffu, pv[0], off);
                pv[1] += __shfl_down_sync(0xffffffffu, pv[1], off);
            }
            if (lane == 0) {
                atomicAdd(&sm->a2[2 * q],     pv[0]);
                atomicAdd(&sm->a2[2 * q + 1], pv[1]);
            }
        }
        __syncthreads();

        // ==== stage 3 (no own barrier; overlaps with stage 5): s2 ====
        if (warp < SAMP) {
            float part = sm->wy2[lane]      * sm->x1[warp][lane]
                       + sm->wy2[lane + 32] * sm->x1[warp][lane + 32];
            #pragma unroll
            for (int off = 16; off; off >>= 1)
                part += __shfl_down_sync(0xffffffffu, part, off);
            if (lane == 0)
                sm->s2[warp] = sig_f(sm->a2[warp] + part + sm->by2);
        }

        // ========= stage 5: v~_k = s0_k * sum_j u~_j wz1[j][k] =========
        {
            u64t acc[SAMP];
            #pragma unroll
            for (int s = 0; s < SAMP; s++) acc[s] = 0ull;
            const int jb = 32 * q;
            #pragma unroll
            for (int jq = 0; jq < 32; jq += 4) {
                u64t wA = w5[(jq >> 2) * 2];
                u64t wB = w5[(jq >> 2) * 2 + 1];
                #pragma unroll
                for (int s = 0; s < SAMP; s++) {
                    ulonglong2 uv = *(const ulonglong2*)&sm->s1u[s][jb + jq];
                    fma2(acc[s], wA, uv.x);
                    fma2(acc[s], wB, uv.y);
                }
            }
            #pragma unroll
            for (int s = 0; s < SAMP; s++)
                sm->scratch[q * 1024 + s * HH + j] = rsum2(acc[s]);
            __syncthreads();
            #pragma unroll
            for (int t = 0; t < 2; t++) {
                int s = 2 * q + t;
                float v = sm->scratch[0 * 1024 + s * HH + j]
                        + sm->scratch[1 * 1024 + s * HH + j]
                        + sm->scratch[2 * 1024 + s * HH + j]
                        + sm->scratch[3 * 1024 + s * HH + j];
                sm->h0v[s][j] = v * sm->s0[s][j];
            }
        }
        __syncthreads();

        // == stage 6: g = s2*(v~ Wy0 + u~ Wy1 + Wy2) + x1 ; update ; norm ==
        {
            u64t acc[SAMP];
            #pragma unroll
            for (int s = 0; s < SAMP; s++) acc[s] = 0ull;
            const int kb = 16 * o6;
            #pragma unroll
            for (int kq = 0; kq < 16; kq += 4) {
                int k = kb + kq;
                u64t w0A = w6[kq],     w0B = w6[kq + 1];
                u64t w1A = w6[kq + 2], w1B = w6[kq + 3];
                #pragma unroll
                for (int s = 0; s < SAMP; s++) {
                    ulonglong2 vv = *(const ulonglong2*)&sm->h0v[s][k];
                    ulonglong2 uu = *(const ulonglong2*)&sm->s1u[s][k];
                    fma2(acc[s], w0A, vv.x);
                    fma2(acc[s], w0B, vv.y);
                    fma2(acc[s], w1A, uu.x);
                    fma2(acc[s], w1B, uu.y);
                }
            }
            #pragma unroll
            for (int s = 0; s < SAMP; s++)
                sm->scratch[o6 * 512 + s * CC + c6] = rsum2(acc[s]);
            __syncthreads();

            const float step = sm->stepv[it];
            const int s = o6;
            float g = 0.0f;
            #pragma unroll
            for (int oo = 0; oo < 8; oo++)
                g += sm->scratch[oo * 512 + s * CC + c6];
            float x1v = sm->x1[s][c6];
            g = sm->s2[s] * (g + sm->wy2[c6]) + x1v;
            float d = sm->z[s][c6] - g;
            sm->x1p[s][c6] = x1v;                 // shadow for stop rollback
            sm->x1 [s][c6] = x1v + step * d;
            float d2 = d * d;
            #pragma unroll
            for (int off = 16; off; off >>= 1)
                d2 += __shfl_down_sync(0xffffffffu, d2, off);
            if (lane == 0) atomicAdd(&sm->nrm2[s], d2);
        }
        __syncthreads();

        // ==== deferred + opportunistic stop check (no per-iter global wait) ====
        if (tid == 0) {
            float sum = 0.0f;
            #pragma unroll
            for (int s = 0; s < SAMP; s++) sum += sqrtf(sm->nrm2[s]);
            atomicAdd(&g_err[it], sum);
            __threadfence();                              // release err before cnt
            unsigned int my = atomicAdd(&g_cnt[it], 1u) + 1u;
            int f = 0;
            if (my == (unsigned)NBLOCKS) {                // we're last at iter it
                __threadfence();                          // acquire
                if (*((volatile float*)&g_err[it]) < TOLV * 1024.0f) f = 1;
            }
            if (it >= 1) {                                // check it-1 (resolved ~1 iter ago)
                unsigned int c = *((volatile unsigned int*)&g_cnt[it - 1]);
                while (c < (unsigned)NBLOCKS) {           // essentially never spins
                    __nanosleep(64);
                    c = *((volatile unsigned int*)&g_cnt[it - 1]);
                }
                __threadfence();                          // acquire: err after cnt
                if (*((volatile float*)&g_err[it - 1]) < TOLV * 1024.0f) f = 2;
            }
            sm->flag = f;
        }
        __syncthreads();   // broadcasts flag; also orders nrm2 read vs next reset
        if (sm->flag) { usePrev = (sm->flag == 2); break; }
    }

    // ---- output: (x1 at stop) + CONVEX*z ----
    for (int idx = tid; idx < SAMP * CC; idx += NTHREADS) {
        int s = idx >> 6, c2 = idx & 63;
        float base = usePrev ? sm->x1p[s][c2] : sm->x1[s][c2];
        out[sbase * CC + idx] = base + sm->z[s][c2];
    }
}

extern "C" void kernel_launch(void* const* d_in, const int* in_sizes, int n_in,
                              void* d_out, int out_size) {
    (void)in_sizes; (void)n_in; (void)out_size;
    cudaFuncSetAttribute(blnn_kernel,
                         cudaFuncAttributeMaxDynamicSharedMemorySize,
                         (int)sizeof(Smem));
    blnn_kernel<<<NBLOCKS, NTHREADS, sizeof(Smem)>>>(
        (const float*)d_in[0], (const float*)d_in[1], (const float*)d_in[2],
        (const float*)d_in[3], (const float*)d_in[4], (const float*)d_in[5],
        (const float*)d_in[6], (const float*)d_in[7], (const float*)d_in[8],
        (float*)d_out);
}

// round 17
// speedup vs baseline: 1.2944x; 1.2944x over previous
#include <cuda_runtime.h>
#include <math.h>

#define NBLOCKS 128
#define NTHREADS 512
#define SAMP 8
#define CC 64
#define HH 128
#define MAX_IT 500
#define TOLV 1e-3f
#define WZ1_S 132   // row stride (floats): mult of 4, ≡4 mod 32 -> LDS.128 conflict-free
#define WY_S  68

typedef unsigned long long u64t;

struct __align__(16) Smem {
    float wz1[HH * WZ1_S];     // clipped Wz1 [j][k]
    float wy0[HH * WY_S];      // [j][c]
    float wy1[HH * WY_S];      // [j][c]
    float wz2[HH];             // clipped
    float wy2[CC];
    float by0[HH];
    float by1[HH];
    float z  [SAMP][CC];
    float x1 [SAMP][CC];
    float h0v[SAMP][HH];       // h0 fwd, v~ bwd
    float s0 [SAMP][HH];       // sigmoid(a0)
    float s1u[SAMP][HH];       // u~ = wz2 * sigmoid(a1)
    float scratch[4096];       // stage partials
    float stepv[MAX_IT];       // 2/(i+1) table
    float a2  [SAMP];
    float s2  [SAMP];
    float nrm2[2][SAMP];       // double-buffered by iteration parity
    float by2;
    int   flag;
};

__device__ unsigned int g_bar_count = 0;
__device__ unsigned int g_bar_gen   = 0;
__device__ float        g_err[MAX_IT];
__device__ unsigned int g_cnt[MAX_IT];

__device__ __forceinline__ u64t pk2(float lo, float hi) {
    u64t r; asm("mov.b64 %0, {%1,%2};" : "=l"(r) : "f"(lo), "f"(hi)); return r;
}
__device__ __forceinline__ void fma2(u64t& d, u64t a, u64t b) {
    asm("fma.rn.f32x2 %0, %1, %2, %0;" : "+l"(d) : "l"(a), "l"(b));
}
__device__ __forceinline__ float rsum2(u64t a) {
    float lo, hi; asm("mov.b64 {%0,%1}, %2;" : "=f"(lo), "=f"(hi) : "l"(a));
    return lo + hi;
}

// EXACT activations (R13 proved approximations delay convergence)
__device__ __forceinline__ void act2(float a, float& sp, float& sg) {
    float e   = __expf(-fabsf(a));
    float inv = __fdividef(1.0f, 1.0f + e);
    sg = (a >= 0.0f) ? inv : e * inv;
    sp = fmaxf(a, 0.0f) + __logf(1.0f + e);
}
__device__ __forceinline__ float sig_f(float a) {
    float e   = __expf(-fabsf(a));
    float inv = __fdividef(1.0f, 1.0f + e);
    return (a >= 0.0f) ? inv : e * inv;
}

// startup-only sense-reversal barrier (device globals persist across graph replays)
__device__ __forceinline__ void grid_barrier() {
    __syncthreads();
    if (threadIdx.x == 0) {
        __threadfence();
        unsigned int gen = *((volatile unsigned int*)&g_bar_gen);
        if (atomicAdd(&g_bar_count, 1u) == (unsigned)(NBLOCKS - 1)) {
            atomicExch(&g_bar_count, 0u);
            __threadfence();
            atomicAdd(&g_bar_gen, 1u);
        } else {
            while (*((volatile unsigned int*)&g_bar_gen) == gen) __nanosleep(32);
        }
    }
    __syncthreads();
}

extern "C" __global__ void __launch_bounds__(NTHREADS, 1)
blnn_kernel(const float* __restrict__ x,   const float* __restrict__ Wy0,
            const float* __restrict__ by0, const float* __restrict__ Wy1,
            const float* __restrict__ by1, const float* __restrict__ Wz1,
            const float* __restrict__ Wy2, const float* __restrict__ by2,
            const float* __restrict__ Wz2, float* __restrict__ out)
{
    extern __shared__ __align__(16) float smem_raw[];
    Smem* sm = (Smem*)smem_raw;
    const int tid  = threadIdx.x;
    const int bx   = blockIdx.x;
    const int lane = tid & 31;
    const int warp = tid >> 5;

    // ---- weights -> SMEM (padded strides, clip Wz* at 0) ----
    for (int idx = tid; idx < HH * HH; idx += NTHREADS) {
        int jj = idx >> 7, kk = idx & (HH - 1);
        sm->wz1[jj * WZ1_S + kk] = fmaxf(Wz1[idx], 0.0f);
    }
    for (int idx = tid; idx < HH * CC; idx += NTHREADS) {
        int jj = idx >> 6, c2 = idx & (CC - 1);
        sm->wy0[jj * WY_S + c2] = Wy0[idx];
        sm->wy1[jj * WY_S + c2] = Wy1[idx];
    }
    if (tid < HH) {
        sm->wz2[tid] = fmaxf(Wz2[tid], 0.0f);
        sm->by0[tid] = by0[tid];
        sm->by1[tid] = by1[tid];
    }
    if (tid < CC) sm->wy2[tid] = Wy2[tid];
    if (tid == 0) sm->by2 = by2[0];
    for (int idx = tid; idx < MAX_IT; idx += NTHREADS)
        sm->stepv[idx] = __fdividef(2.0f, (float)(idx + 1));

    const int sbase = bx * SAMP;
    for (int idx = tid; idx < SAMP * CC; idx += NTHREADS) {
        sm->z [idx >> 6][idx & 63] = x[sbase * CC + idx];
        sm->x1[idx >> 6][idx & 63] = 1.0f;
    }
    // re-zero our stripe of the per-iteration accumulators (graph replays!)
    if (tid == 0) {
        for (int idx = bx; idx < MAX_IT; idx += NBLOCKS) {
            *((volatile float*)&g_err[idx]) = 0.0f;
            *((volatile unsigned int*)&g_cnt[idx]) = 0u;
        }
    }
    grid_barrier();   // slots zeroed everywhere before any block posts

    const int j  = tid & (HH - 1);   // stages 1/2/5: output feature index
    const int q  = tid >> 7;         // 0..3: reduction quarter
    const int c6 = tid & (CC - 1);   // stage 6: output c
    const int o6 = tid >> 6;         // 0..7: stage 6 reduction eighth / sample

    // ---- register-resident weights for stages 5 & 6 (thread-invariant) ----
    u64t w5[16];
    {
        const int jb = 32 * q;
        #pragma unroll
        for (int jq = 0; jq < 32; jq += 4) {
            const float* col = &sm->wz1[(jb + jq) * WZ1_S + j];
            w5[(jq >> 2) * 2]     = pk2(col[0],         col[WZ1_S]);
            w5[(jq >> 2) * 2 + 1] = pk2(col[2 * WZ1_S], col[3 * WZ1_S]);
        }
    }
    u64t w6[16];
    {
        const int kb = 16 * o6;
        #pragma unroll
        for (int kq = 0; kq < 16; kq += 4) {
            int k = kb + kq;
            const float* p0 = &sm->wy0[k * WY_S + c6];
            const float* p1 = &sm->wy1[k * WY_S + c6];
            w6[kq]     = pk2(p0[0],        p0[WY_S]);
            w6[kq + 1] = pk2(p0[2 * WY_S], p0[3 * WY_S]);
            w6[kq + 2] = pk2(p1[0],        p1[WY_S]);
            w6[kq + 3] = pk2(p1[2 * WY_S], p1[3 * WY_S]);
        }
    }

    int it = 0;
    for (; it < MAX_IT; ++it) {
        const int par = it & 1;
        if (tid < SAMP) { sm->a2[tid] = 0.0f; sm->nrm2[par][tid] = 0.0f; }

        // ================= stage 1: a0 = Wy0 x1 + by0 =================
        {
            u64t acc[SAMP];
            #pragma unroll
            for (int s = 0; s < SAMP; s++) acc[s] = 0ull;
            const float* wrow = &sm->wy0[j * WY_S + 16 * q];
            const int cb = 16 * q;
            #pragma unroll
            for (int cq = 0; cq < 16; cq += 4) {
                ulonglong2 w = *(const ulonglong2*)(wrow + cq);
                #pragma unroll
                for (int s = 0; s < SAMP; s++) {
                    ulonglong2 xv = *(const ulonglong2*)&sm->x1[s][cb + cq];
                    fma2(acc[s], w.x, xv.x);
                    fma2(acc[s], w.y, xv.y);
                }
            }
            #pragma unroll
            for (int s = 0; s < SAMP; s++)
                sm->scratch[q * 1024 + s * HH + j] = rsum2(acc[s]);
            __syncthreads();
            #pragma unroll
            for (int t = 0; t < 2; t++) {
                int s = 2 * q + t;
                float a = sm->scratch[0 * 1024 + s * HH + j]
                        + sm->scratch[1 * 1024 + s * HH + j]
                        + sm->scratch[2 * 1024 + s * HH + j]
                        + sm->scratch[3 * 1024 + s * HH + j] + sm->by0[j];
                float sp, sg;
                act2(a, sp, sg);
                sm->h0v[s][j] = sp;
                sm->s0 [s][j] = sg;
            }
        }
        __syncthreads();

        // ====== stage 2: a1 = Wz1p h0 + Wy1 x1 + by1 ; u~ ; a2 partial ======
        {
            u64t acc[SAMP];
            #pragma unroll
            for (int s = 0; s < SAMP; s++) acc[s] = 0ull;
            const float* wzrow = &sm->wz1[j * WZ1_S + 32 * q];
            const int kb = 32 * q;
            #pragma unroll
            for (int kq = 0; kq < 32; kq += 4) {
                ulonglong2 w = *(const ulonglong2*)(wzrow + kq);
                #pragma unroll
                for (int s = 0; s < SAMP; s++) {
                    ulonglong2 hv = *(const ulonglong2*)&sm->h0v[s][kb + kq];
                    fma2(acc[s], w.x, hv.x);
                    fma2(acc[s], w.y, hv.y);
                }
            }
            const float* wyrow = &sm->wy1[j * WY_S + 16 * q];
            const int cb = 16 * q;
            #pragma unroll
            for (int cq = 0; cq < 16; cq += 4) {
                ulonglong2 w = *(const ulonglong2*)(wyrow + cq);
                #pragma unroll
                for (int s = 0; s < SAMP; s++) {
                    ulonglong2 xv = *(const ulonglong2*)&sm->x1[s][cb + cq];
                    fma2(acc[s], w.x, xv.x);
                    fma2(acc[s], w.y, xv.y);
                }
            }
            #pragma unroll
            for (int s = 0; s < SAMP; s++)
                sm->scratch[q * 1024 + s * HH + j] = rsum2(acc[s]);
            __syncthreads();
            const float wz2j = sm->wz2[j];
            float pv[2];
            #pragma unroll
            for (int t = 0; t < 2; t++) {
                int s = 2 * q + t;
                float a = sm->scratch[0 * 1024 + s * HH + j]
                        + sm->scratch[1 * 1024 + s * HH + j]
                        + sm->scratch[2 * 1024 + s * HH + j]
                        + sm->scratch[3 * 1024 + s * HH + j] + sm->by1[j];
                float sp, sg;
                act2(a, sp, sg);
                sm->s1u[s][j] = wz2j * sg;     // u~
                pv[t] = wz2j * sp;             // wz2 * h1
            }
            #pragma unroll
            for (int off = 16; off; off >>= 1) {
                pv[0] += __shfl_down_sync(0xffffffffu, pv[0], off);
                pv[1] += __shfl_down_sync(0xffffffffu, pv[1], off);
            }
            if (lane == 0) {
                atomicAdd(&sm->a2[2 * q],     pv[0]);
                atomicAdd(&sm->a2[2 * q + 1], pv[1]);
            }
        }
        __syncthreads();

        // -- checker (tid 256, warp 8): issue early read of last iter's err.
        //    Consumed only after stage-5 compute -> L2 latency hidden.
        float e1 = 1e30f;
        if (tid == 256 && it > 0)
            e1 = *((volatile float*)&g_err[it - 1]);

        // ==== stage 3 (no own barrier; overlaps with stage 5): s2 ====
        if (warp < SAMP) {
            float part = sm->wy2[lane]      * sm->x1[warp][lane]
                       + sm->wy2[lane + 32] * sm->x1[warp][lane + 32];
            #pragma unroll
            for (int off = 16; off; off >>= 1)
                part += __shfl_down_sync(0xffffffffu, part, off);
            if (lane == 0)
                sm->s2[warp] = sig_f(sm->a2[warp] + part + sm->by2);
        }

        // ========= stage 5: v~_k = s0_k * sum_j u~_j wz1[j][k] =========
        {
            u64t acc[SAMP];
            #pragma unroll
            for (int s = 0; s < SAMP; s++) acc[s] = 0ull;
            const int jb = 32 * q;
            #pragma unroll
            for (int jq = 0; jq < 32; jq += 4) {
                u64t wA = w5[(jq >> 2) * 2];
                u64t wB = w5[(jq >> 2) * 2 + 1];
                #pragma unroll
                for (int s = 0; s < SAMP; s++) {
                    ulonglong2 uv = *(const ulonglong2*)&sm->s1u[s][jb + jq];
                    fma2(acc[s], wA, uv.x);
                    fma2(acc[s], wB, uv.y);
                }
            }
            #pragma unroll
            for (int s = 0; s < SAMP; s++)
                sm->scratch[q * 1024 + s * HH + j] = rsum2(acc[s]);
            __syncthreads();
            #pragma unroll
            for (int t = 0; t < 2; t++) {
                int s = 2 * q + t;
                float v = sm->scratch[0 * 1024 + s * HH + j]
                        + sm->scratch[1 * 1024 + s * HH + j]
                        + sm->scratch[2 * 1024 + s * HH + j]
                        + sm->scratch[3 * 1024 + s * HH + j];
                sm->h0v[s][j] = v * sm->s0[s][j];
            }
        }

        // -- checker resolves the flag (common path: e1 >= TOL -> 0 work).
        //    err terms are nonnegative: a PARTIAL sum >= TOL proves not-converged,
        //    so completeness (cnt==128) is only verified when e1 < TOL.
        if (tid == 256) {
            int f = 0;
            if (it > 0 && e1 < TOLV * 1024.0f) {          // rare: near convergence
                unsigned int c = *((volatile unsigned int*)&g_cnt[it - 1]);
                while (c < (unsigned)NBLOCKS) {
                    __nanosleep(64);
                    c = *((volatile unsigned int*)&g_cnt[it - 1]);
                }
                __threadfence();                          // acquire: err after cnt
                float ef = *((volatile float*)&g_err[it - 1]);
                f = (ef < TOLV * 1024.0f) ? 1 : 0;
            }
            sm->flag = f;
        }
        __syncthreads();   // stage-5 end sync also publishes flag
        // stop BEFORE stage 6: x1 currently holds x1_{it}, exactly the
        // reference's frozen value when done flips at iteration it-1.
        if (sm->flag) break;

        // == stage 6: g = s2*(v~ Wy0 + u~ Wy1 + Wy2) + x1 ; update ; norm ==
        {
            u64t acc[SAMP];
            #pragma unroll
            for (int s = 0; s < SAMP; s++) acc[s] = 0ull;
            const int kb = 16 * o6;
            #pragma unroll
            for (int kq = 0; kq < 16; kq += 4) {
                int k = kb + kq;
                u64t w0A = w6[kq],     w0B = w6[kq + 1];
                u64t w1A = w6[kq + 2], w1B = w6[kq + 3];
                #pragma unroll
                for (int s = 0; s < SAMP; s++) {
                    ulonglong2 vv = *(const ulonglong2*)&sm->h0v[s][k];
                    ulonglong2 uu = *(const ulonglong2*)&sm->s1u[s][k];
                    fma2(acc[s], w0A, vv.x);
                    fma2(acc[s], w0B, vv.y);
                    fma2(acc[s], w1A, uu.x);
                    fma2(acc[s], w1B, uu.y);
                }
            }
            #pragma unroll
            for (int s = 0; s < SAMP; s++)
                sm->scratch[o6 * 512 + s * CC + c6] = rsum2(acc[s]);
            __syncthreads();

            const float step = sm->stepv[it];
            const int s = o6;
            float g = 0.0f;
            #pragma unroll
            for (int oo = 0; oo < 8; oo++)
                g += sm->scratch[oo * 512 + s * CC + c6];
            float x1v = sm->x1[s][c6];
            g = sm->s2[s] * (g + sm->wy2[c6]) + x1v;
            float d = sm->z[s][c6] - g;
            sm->x1[s][c6] = x1v + step * d;
            float d2 = d * d;
            #pragma unroll
            for (int off = 16; off; off >>= 1)
                d2 += __shfl_down_sync(0xffffffffu, d2, off);
            if (lane == 0) atomicAdd(&sm->nrm2[par][s], d2);
        }
        __syncthreads();

        // ==== post (fire-and-forget: RED + membar + RED, no waiting) ====
        if (tid == 0) {
            float sum = 0.0f;
            #pragma unroll
            for (int s = 0; s < SAMP; s++) sum += sqrtf(sm->nrm2[par][s]);
            atomicAdd(&g_err[it], sum);     // result unused -> RED
            __threadfence();                // release err before cnt
            atomicAdd(&g_cnt[it], 1u);      // result unused -> RED
        }
        // no sync needed: nrm2 is parity-double-buffered; next iteration's
        // reset touches the other buffer, and a2 was consumed two syncs ago.
    }

    // ---- output: x1 + CONVEX*z ----
    for (int idx = tid; idx < SAMP * CC; idx += NTHREADS) {
        int s = idx >> 6, c2 = idx & 63;
        out[sbase * CC + idx] = sm->x1[s][c2] + sm->z[s][c2];
    }
}

extern "C" void kernel_launch(void* const* d_in, const int* in_sizes, int n_in,
                              void* d_out, int out_size) {
    (void)in_sizes; (void)n_in; (void)out_size;
    cudaFuncSetAttribute(blnn_kernel,
                         cudaFuncAttributeMaxDynamicSharedMemorySize,
                         (int)sizeof(Smem));
    blnn_kernel<<<NBLOCKS, NTHREADS, sizeof(Smem)>>>(
        (const float*)d_in[0], (const float*)d_in[1], (const float*)d_in[2],
        (const float*)d_in[3], (const float*)d_in[4], (const float*)d_in[5],
        (const float*)d_in[6], (const float*)d_in[7], (const float*)d_in[8],
        (float*)d_out);
}